// round 2
// baseline (speedup 1.0000x reference)
#include <cuda_runtime.h>
#include <math.h>

// ---------------- problem constants ----------------
#define BSZ     2
#define SEQL    4096
#define DMODEL  768
#define DSTATE  128
#define HD      64
#define DIN     1536
#define NH      24
#define DXBC    1792          // DIN + 2*DSTATE
#define DPROJ   3352          // 2*DIN + 2*DSTATE + NH
#define CHUNKQ  128
#define NCH     32            // SEQL / CHUNKQ
#define NROWS   (BSZ*SEQL)    // 8192
#define NBC     (BSZ*NCH)     // 64

// ---------------- scratch (static device memory; no runtime allocs) ----------------
__device__ float g_zx[(size_t)NROWS*DPROJ];            // in_proj output  (110 MB)
__device__ float g_xbc[(size_t)NROWS*DXBC];            // conv+silu out   (59 MB)
__device__ float g_dt[NROWS*NH];                       // softplus dt
__device__ float g_acum[NROWS*NH];                     // per-chunk cumsum of dt*A
__device__ float g_alast[NBC*NH];                      // chunk-final acum
__device__ float g_cb[(size_t)NBC*CHUNKQ*CHUNKQ];      // C@B^T per chunk (4.2 MB)
__device__ float g_states[(size_t)NBC*NH*HD*DSTATE];   // per-chunk states (50 MB)
__device__ float g_prev[(size_t)NBC*NH*HD*DSTATE];     // state entering chunk (50 MB)
__device__ float g_y[(size_t)NROWS*DIN];               // ssd output / normalized y (50 MB)

// ---------------- generic tiled fp32 GEMM: C = A(MxK) * B(NxK)^T ----------------
// EP=1: C = sigmoid(gate1)*C + feat  (final residual epilogue)
template<int EP>
__global__ void gemm_nt(const float* __restrict__ A, const float* __restrict__ B,
                        float* __restrict__ C, int M, int N, int K,
                        const float* __restrict__ feat, const float* __restrict__ gate1)
{
    __shared__ float As[16][64];
    __shared__ float Bs[16][64];
    const int tid  = threadIdx.x;
    const int m0   = blockIdx.y * 64;
    const int n0   = blockIdx.x * 64;
    const int lrow = tid >> 2;          // 0..63
    const int lk   = (tid & 3) * 4;     // 0,4,8,12
    const int ty   = tid >> 4;          // 0..15
    const int tx   = tid & 15;          // 0..15

    float acc[4][4] = {};
    for (int k0 = 0; k0 < K; k0 += 16) {
        float4 av = *(const float4*)(A + (size_t)(m0 + lrow) * K + k0 + lk);
        As[lk+0][lrow] = av.x; As[lk+1][lrow] = av.y;
        As[lk+2][lrow] = av.z; As[lk+3][lrow] = av.w;
        int bn = n0 + lrow;
        float4 bv = make_float4(0.f, 0.f, 0.f, 0.f);
        if (bn < N) bv = *(const float4*)(B + (size_t)bn * K + k0 + lk);
        Bs[lk+0][lrow] = bv.x; Bs[lk+1][lrow] = bv.y;
        Bs[lk+2][lrow] = bv.z; Bs[lk+3][lrow] = bv.w;
        __syncthreads();
        #pragma unroll
        for (int kk = 0; kk < 16; kk++) {
            float4 a = *(const float4*)&As[kk][ty*4];
            float4 b = *(const float4*)&Bs[kk][tx*4];
            acc[0][0] += a.x*b.x; acc[0][1] += a.x*b.y; acc[0][2] += a.x*b.z; acc[0][3] += a.x*b.w;
            acc[1][0] += a.y*b.x; acc[1][1] += a.y*b.y; acc[1][2] += a.y*b.z; acc[1][3] += a.y*b.w;
            acc[2][0] += a.z*b.x; acc[2][1] += a.z*b.y; acc[2][2] += a.z*b.z; acc[2][3] += a.z*b.w;
            acc[3][0] += a.w*b.x; acc[3][1] += a.w*b.y; acc[3][2] += a.w*b.z; acc[3][3] += a.w*b.w;
        }
        __syncthreads();
    }
    float g = 0.f;
    if (EP) g = 1.f / (1.f + expf(-gate1[0]));
    #pragma unroll
    for (int i = 0; i < 4; i++) {
        int m = m0 + ty*4 + i;
        #pragma unroll
        for (int j = 0; j < 4; j++) {
            int n = n0 + tx*4 + j;
            if (n < N) {
                float v = acc[i][j];
                if (EP) v = g * v + feat[(size_t)m * N + n];
                C[(size_t)m * N + n] = v;
            }
        }
    }
}

// ---------------- depthwise causal conv (width 4) + bias + SiLU ----------------
__global__ void conv_silu_kernel(const float* __restrict__ cw, const float* __restrict__ cb)
{
    int idx = blockIdx.x * blockDim.x + threadIdx.x;
    if (idx >= NROWS * DXBC) return;
    int ch  = idx % DXBC;
    int row = idx / DXBC;
    int l   = row % SEQL;
    float acc = cb[ch];
    #pragma unroll
    for (int k = 0; k < 4; k++) {
        int ls = l + k - 3;
        if (ls >= 0)
            acc += cw[ch*4 + k] * g_zx[(size_t)(row + k - 3) * DPROJ + DIN + ch];
    }
    g_xbc[idx] = acc / (1.f + expf(-acc));   // silu
}

// ---------------- dt = softplus(raw + dt_bias) ----------------
__global__ void dt_kernel(const float* __restrict__ dt_bias)
{
    int idx = blockIdx.x * blockDim.x + threadIdx.x;
    if (idx >= NROWS * NH) return;
    int h   = idx % NH;
    int row = idx / NH;
    float v = g_zx[(size_t)row * DPROJ + (DIN + DXBC) + h] + dt_bias[h];
    g_dt[idx] = (v > 20.f) ? v : log1pf(expf(v));
}

// ---------------- per-chunk inclusive cumsum of Adt = dt * (-exp(A_log)) ----------------
__global__ void acum_kernel(const float* __restrict__ A_log)
{
    int h  = blockIdx.x % NH;
    int bc = blockIdx.x / NH;
    int l  = threadIdx.x;   // 128
    __shared__ float s[CHUNKQ];
    float Ah = -expf(A_log[h]);
    int row = bc * CHUNKQ + l;
    s[l] = g_dt[row * NH + h] * Ah;
    __syncthreads();
    for (int off = 1; off < CHUNKQ; off <<= 1) {
        float v = (l >= off) ? s[l - off] : 0.f;
        __syncthreads();
        s[l] += v;
        __syncthreads();
    }
    g_acum[row * NH + h] = s[l];
    if (l == CHUNKQ - 1) g_alast[bc * NH + h] = s[l];
}

// ---------------- CB[l,s] = sum_n C[l,n]*B[s,n] per chunk ----------------
#define CB_SMEM_BYTES ((CHUNKQ*CHUNKQ + CHUNKQ*132) * 4)
__global__ void cb_kernel()
{
    extern __shared__ float sm[];
    float* Cs  = sm;                    // [128][128]  l-major
    float* BsT = sm + CHUNKQ*CHUNKQ;    // [128][132]  n-major (transposed, padded)
    int bc  = blockIdx.x;
    int tid = threadIdx.x;              // 256
    int row0 = bc * CHUNKQ;
    for (int i = tid; i < CHUNKQ*CHUNKQ; i += 256) {
        int l = i >> 7, n = i & 127;
        const float* base = &g_xbc[(size_t)(row0 + l) * DXBC];
        Cs[i]            = base[DIN + DSTATE + n];
        BsT[n*132 + l]   = base[DIN + n];
    }
    __syncthreads();
    int l  = tid >> 1;
    int s0 = (tid & 1) * 64;
    float acc[64] = {};
    for (int n = 0; n < 128; n++) {
        float cv = Cs[l*128 + n];
        const float4* bp = (const float4*)&BsT[n*132 + s0];
        #pragma unroll
        for (int j4 = 0; j4 < 16; j4++) {
            float4 b = bp[j4];
            acc[4*j4+0] += cv*b.x; acc[4*j4+1] += cv*b.y;
            acc[4*j4+2] += cv*b.z; acc[4*j4+3] += cv*b.w;
        }
    }
    float* outp = &g_cb[(size_t)bc*CHUNKQ*CHUNKQ + l*CHUNKQ + s0];
    #pragma unroll
    for (int j4 = 0; j4 < 16; j4++)
        ((float4*)outp)[j4] = make_float4(acc[4*j4], acc[4*j4+1], acc[4*j4+2], acc[4*j4+3]);
}

// ---------------- states[p,n] = sum_l dt[l]*exp(Alast-Acum[l]) * x[l,p] * B[l,n] ----------------
#define ST_SMEM_BYTES ((128 + 8192 + 16384) * 4)
__global__ void states_kernel()
{
    extern __shared__ float sm[];
    float* wfac = sm;            // [128]
    float* xw   = sm + 128;      // [128][64]
    float* Bsm  = xw + 8192;     // [128][128]
    int h  = blockIdx.x % NH;
    int bc = blockIdx.x / NH;
    int tid = threadIdx.x;       // 256
    int row0 = bc * CHUNKQ;
    float alast = g_alast[bc*NH + h];
    if (tid < 128)
        wfac[tid] = g_dt[(row0+tid)*NH + h] * expf(alast - g_acum[(row0+tid)*NH + h]);
    __syncthreads();
    for (int i = tid; i < 8192; i += 256) {
        int l = i >> 6, p = i & 63;
        xw[i] = g_xbc[(size_t)(row0+l)*DXBC + h*HD + p] * wfac[l];
    }
    for (int i = tid; i < 16384; i += 256) {
        int l = i >> 7, n = i & 127;
        Bsm[i] = g_xbc[(size_t)(row0+l)*DXBC + DIN + n];
    }
    __syncthreads();
    int tp = tid >> 4, tn = tid & 15;
    int p0 = tp*4, n0 = tn*8;
    float acc[4][8] = {};
    for (int l = 0; l < 128; l++) {
        float4 a  = *(const float4*)&xw[l*64 + p0];
        float4 b0 = *(const float4*)&Bsm[l*128 + n0];
        float4 b1 = *(const float4*)&Bsm[l*128 + n0 + 4];
        float av[4] = {a.x, a.y, a.z, a.w};
        float bv[8] = {b0.x, b0.y, b0.z, b0.w, b1.x, b1.y, b1.z, b1.w};
        #pragma unroll
        for (int i = 0; i < 4; i++)
            #pragma unroll
            for (int j = 0; j < 8; j++)
                acc[i][j] += av[i] * bv[j];
    }
    float* outb = &g_states[((size_t)(bc*NH) + h) * HD * DSTATE];
    #pragma unroll
    for (int i = 0; i < 4; i++) {
        *(float4*)&outb[(p0+i)*DSTATE + n0]     = make_float4(acc[i][0], acc[i][1], acc[i][2], acc[i][3]);
        *(float4*)&outb[(p0+i)*DSTATE + n0 + 4] = make_float4(acc[i][4], acc[i][5], acc[i][6], acc[i][7]);
    }
}

// ---------------- inter-chunk state recurrence: prev[c] = prev[c-1]*exp(Alast[c-1]) + states[c-1] ----------------
__global__ void scan_kernel()
{
    int h = blockIdx.x % NH;
    int b = blockIdx.x / NH;
    int tid = threadIdx.x;   // 512
    float S[16];
    #pragma unroll
    for (int i = 0; i < 16; i++) S[i] = 0.f;
    for (int c = 0; c < NCH; c++) {
        int bc = b*NCH + c;
        size_t base = ((size_t)(bc*NH) + h) * HD * DSTATE;
        float ed = expf(g_alast[bc*NH + h]);
        #pragma unroll
        for (int i = 0; i < 16; i++) {
            int idx = tid + i*512;
            float st = g_states[base + idx];
            g_prev[base + idx] = S[i];
            S[i] = S[i]*ed + st;
        }
    }
}

// ---------------- fused Y kernel: Y_off + Y_diag + D*x per (chunk,head) ----------------
#define Y_SMEM_BYTES ((128*129*2 + 8192 + 128*68 + 256) * 4)   // 200704 B
__global__ void y_kernel(const float* __restrict__ Dv)
{
    extern __shared__ float sm[];
    float* CBp    = sm;                 // [128][129]  (pad -> conflict-free per-lane rows)
    float* Csp    = CBp + 128*129;      // [128][129]
    float* xs     = Csp + 128*129;      // [128][64]  raw x (no dt)
    float* prevT  = xs + 8192;          // [128][68]  prev transposed [n][p]
    float* acum_s = prevT + 128*68;     // [128]
    float* dt_s   = acum_s + 128;       // [128]
    int h  = blockIdx.x % NH;
    int bc = blockIdx.x / NH;
    int tid = threadIdx.x;              // 128
    int row0 = bc * CHUNKQ;

    acum_s[tid] = g_acum[(row0+tid)*NH + h];
    dt_s[tid]   = g_dt[(row0+tid)*NH + h];
    for (int i = tid; i < 128*128; i += 128) {
        int l = i >> 7, c = i & 127;
        CBp[l*129 + c] = g_cb[(size_t)bc*CHUNKQ*CHUNKQ + i];
        Csp[l*129 + c] = g_xbc[(size_t)(row0+l)*DXBC + DIN + DSTATE + c];
    }
    size_t pbase = ((size_t)(bc*NH) + h) * HD * DSTATE;
    for (int i = tid; i < 8192; i += 128) {
        int p = i >> 7, n = i & 127;
        prevT[n*68 + p] = g_prev[pbase + i];
        int l2 = i >> 6, pp = i & 63;
        xs[i] = g_xbc[(size_t)(row0+l2)*DXBC + h*HD + pp];
    }
    __syncthreads();

    int l = tid;
    float la  = acum_s[l];
    float eAl = expf(la);
    float acc[64];
    #pragma unroll
    for (int p = 0; p < 64; p++) acc[p] = 0.f;

    // Y_off (un-scaled): sum_n C[l,n] * prev[p,n]
    for (int n = 0; n < 128; n++) {
        float cv = Csp[l*129 + n];
        const float4* pr = (const float4*)&prevT[n*68];
        #pragma unroll
        for (int p4 = 0; p4 < 16; p4++) {
            float4 v = pr[p4];
            acc[4*p4+0] += cv*v.x; acc[4*p4+1] += cv*v.y;
            acc[4*p4+2] += cv*v.z; acc[4*p4+3] += cv*v.w;
        }
    }
    // scale by exp(Acum[l]) and add D[h]*x[l,p]
    {
        float dval = Dv[h];
        const float4* xr = (const float4*)&xs[l*64];
        #pragma unroll
        for (int p4 = 0; p4 < 16; p4++) {
            float4 v = xr[p4];
            acc[4*p4+0] = acc[4*p4+0]*eAl + dval*v.x;
            acc[4*p4+1] = acc[4*p4+1]*eAl + dval*v.y;
            acc[4*p4+2] = acc[4*p4+2]*eAl + dval*v.z;
            acc[4*p4+3] = acc[4*p4+3]*eAl + dval*v.w;
        }
    }
    // Y_diag: sum_{s<=l} CB[l,s]*exp(Acum[l]-Acum[s])*dt[s]*x[s,p]
    for (int s = 0; s <= l; s++) {
        float w = CBp[l*129 + s] * expf(la - acum_s[s]) * dt_s[s];
        const float4* xv = (const float4*)&xs[s*64];
        #pragma unroll
        for (int p4 = 0; p4 < 16; p4++) {
            float4 v = xv[p4];
            acc[4*p4+0] += w*v.x; acc[4*p4+1] += w*v.y;
            acc[4*p4+2] += w*v.z; acc[4*p4+3] += w*v.w;
        }
    }
    float4* yo = (float4*)&g_y[(size_t)(row0+l)*DIN + h*HD];
    #pragma unroll
    for (int p4 = 0; p4 < 16; p4++)
        yo[p4] = make_float4(acc[4*p4], acc[4*p4+1], acc[4*p4+2], acc[4*p4+3]);
}

// ---------------- gating + RMSNorm ----------------
__global__ void norm_kernel(const float* __restrict__ norm_w)
{
    __shared__ float tbuf[DIN];
    __shared__ float red[256];
    int row = blockIdx.x;
    int tid = threadIdx.x;   // 256
    float partial = 0.f;
    for (int i = tid; i < DIN; i += 256) {
        float yv = g_y[(size_t)row*DIN + i];
        float zv = g_zx[(size_t)row*DPROJ + i];
        float t  = yv * (zv / (1.f + expf(-zv)));
        tbuf[i] = t;
        partial += t*t;
    }
    red[tid] = partial;
    __syncthreads();
    for (int s = 128; s > 0; s >>= 1) {
        if (tid < s) red[tid] += red[tid + s];
        __syncthreads();
    }
    float scale = rsqrtf(red[0] / (float)DIN + 1e-5f);
    for (int i = tid; i < DIN; i += 256)
        g_y[(size_t)row*DIN + i] = tbuf[i] * scale * norm_w[i];
}

// ---------------- launch ----------------
extern "C" void kernel_launch(void* const* d_in, const int* in_sizes, int n_in,
                              void* d_out, int out_size)
{
    const float* feature = (const float*)d_in[0];
    const float* gate1   = (const float*)d_in[1];
    const float* in_w    = (const float*)d_in[2];
    const float* conv_w  = (const float*)d_in[3];
    const float* conv_b  = (const float*)d_in[4];
    const float* dt_bias = (const float*)d_in[5];
    const float* A_log   = (const float*)d_in[6];
    const float* Dv      = (const float*)d_in[7];
    const float* norm_w  = (const float*)d_in[8];
    const float* out_w   = (const float*)d_in[9];
    float* out = (float*)d_out;

    void* p_zx; cudaGetSymbolAddress(&p_zx, g_zx);
    void* p_y;  cudaGetSymbolAddress(&p_y,  g_y);

    cudaFuncSetAttribute(cb_kernel,     cudaFuncAttributeMaxDynamicSharedMemorySize, CB_SMEM_BYTES);
    cudaFuncSetAttribute(states_kernel, cudaFuncAttributeMaxDynamicSharedMemorySize, ST_SMEM_BYTES);
    cudaFuncSetAttribute(y_kernel,      cudaFuncAttributeMaxDynamicSharedMemorySize, Y_SMEM_BYTES);

    // 1. zxbcdt = feature @ in_proj_w^T
    gemm_nt<0><<<dim3((DPROJ + 63)/64, NROWS/64), 256>>>(
        feature, in_w, (float*)p_zx, NROWS, DPROJ, DMODEL, nullptr, nullptr);
    // 2. conv + silu on xBC slice
    conv_silu_kernel<<<(NROWS*DXBC + 255)/256, 256>>>(conv_w, conv_b);
    // 3. dt
    dt_kernel<<<(NROWS*NH + 255)/256, 256>>>(dt_bias);
    // 4. per-chunk cumsum of dt*A
    acum_kernel<<<NBC*NH, CHUNKQ>>>(A_log);
    // 5. CB per chunk
    cb_kernel<<<NBC, 256, CB_SMEM_BYTES>>>();
    // 6. chunk states
    states_kernel<<<NBC*NH, 256, ST_SMEM_BYTES>>>();
    // 7. inter-chunk recurrence
    scan_kernel<<<BSZ*NH, 512>>>();
    // 8. Y = Y_diag + Y_off + D*x
    y_kernel<<<NBC*NH, CHUNKQ, Y_SMEM_BYTES>>>(Dv);
    // 9. gating + RMSNorm
    norm_kernel<<<NROWS, 256>>>(norm_w);
    // 10. out = sigmoid(gate1) * (y @ out_proj_w^T) + feature
    gemm_nt<1><<<dim3(DMODEL/64, NROWS/64), 256>>>(
        (const float*)p_y, out_w, out, NROWS, DMODEL, DIN, feature, gate1);
}